// round 13
// baseline (speedup 1.0000x reference)
#include <cuda_runtime.h>
#include <cstdint>
#include <cstddef>

#define BATCH 256
#define ANUM  128
#define NBNUM 256
#define DNUM  16
#define FA    64
#define FB    32
#define FPC   256
#define R_NEI  (BATCH*ANUM*DNUM)   // 524288
#define R_ATOM (BATCH*ANUM)        // 32768
#define R_BOND (BATCH*NBNUM)       // 65536
#define ATOM_OUT_ELEMS ((long long)R_ATOM*FPC)
#define NEI_OUT_ELEMS  ((long long)R_NEI*FPC)
#define BN_EPS 1e-6f
#define SLOPE  0.01f

// ---------------- device scratch ----------------
__device__ float g_P[(size_t)R_ATOM * FPC];   // 33.5 MB
__device__ float g_Q[(size_t)R_BOND * FPC];   // 67 MB
__device__ float g_cntA[R_ATOM];
__device__ float g_cntB[R_BOND];
__device__ int   g_csr[R_NEI];                // per-batch CSR: bond idx lists
__device__ int   g_offs[R_ATOM];              // per-batch CSR offsets
__device__ float g_Sx[64*64];                 // atom 2nd moment
__device__ float g_mx[64];                    // atom 1st moment
__device__ float g_Sab[64*32];                // raw-feature cross moment
__device__ float g_sum1[FPC];                 // nei sum t  (weighted epilogues)
__device__ float g_sq1[FPC];                  // nei sum t^2 (minus cross)
__device__ float g_scale[2][FPC];
__device__ float g_shift[2][FPC];

// Shared-memory budgets (floats), mirroring the body layouts EXACTLY.
// gemm: ws K*256 + xs2 (K*64 u64 = K*128 floats) + cw 64 + ssum/ssq 512
#define SMEM_GEMM_F   (64*FPC + 64*64*2 + 64 + 2*FPC)        // 25152
#define SMEM_CROSS_F  (128*64 + 8*2048 + 128 + 128)          // 24832
#define SMEM_MID_F    (SMEM_CROSS_F > SMEM_GEMM_F ? SMEM_CROSS_F : SMEM_GEMM_F)

// ---------------- packed f32x2 helpers ----------------
__device__ __forceinline__ unsigned long long pack2(float lo, float hi) {
    unsigned long long r;
    asm("mov.b64 %0, {%1,%2};" : "=l"(r) : "f"(lo), "f"(hi));
    return r;
}
__device__ __forceinline__ void fma2(unsigned long long& d,
                                     unsigned long long a,
                                     unsigned long long b) {
    asm("fma.rn.f32x2 %0, %1, %2, %0;" : "+l"(d) : "l"(a), "l"(b));
}
__device__ __forceinline__ float2 unpack2(unsigned long long v) {
    float2 r;
    asm("mov.b64 {%0,%1}, %2;" : "=f"(r.x), "=f"(r.y) : "l"(v));
    return r;
}

// ---------------- zero scratch ----------------
__global__ void zero_kernel() {
    const int tid = threadIdx.x;
    for (int i = tid; i < 64*64; i += 256) g_Sx[i] = 0.f;
    for (int i = tid; i < 64*32; i += 256) g_Sab[i] = 0.f;
    if (tid < 64) g_mx[tid] = 0.f;
    g_sum1[tid] = 0.f;
    g_sq1[tid]  = 0.f;
}

// ---------------- Sx body: Sx += X_blk^T X_blk, mx += sum(X_blk) ----------
__device__ __forceinline__
void sx_body(float* smem, const float4* __restrict__ X, int vbid)
{
    float (*xs)[64] = (float(*)[64])smem;   // 32 x 64
    const int tid = threadIdx.x;
    const int i0 = (tid >> 4) * 4;
    const int j0 = (tid & 15) * 4;

    float acc[4][4];
    #pragma unroll
    for (int a = 0; a < 4; ++a)
        #pragma unroll
        for (int b = 0; b < 4; ++b) acc[a][b] = 0.f;
    float mp[4] = {0.f, 0.f, 0.f, 0.f};

    const int base = vbid * 128;
    for (int s = 0; s < 128; s += 32) {
        for (int idx = tid; idx < 512; idx += 256) {
            int row = idx >> 4, q = idx & 15;
            float4 v = X[(size_t)(base + s + row) * 16 + q];
            *(float4*)&xs[row][q * 4] = v;
        }
        __syncthreads();
        for (int k = 0; k < 32; ++k) {
            float xi[4], xj[4];
            #pragma unroll
            for (int a = 0; a < 4; ++a) { xi[a] = xs[k][i0 + a]; xj[a] = xs[k][j0 + a]; }
            #pragma unroll
            for (int a = 0; a < 4; ++a)
                #pragma unroll
                for (int b = 0; b < 4; ++b) acc[a][b] += xi[a] * xj[b];
            if ((tid >> 4) == 0) {
                #pragma unroll
                for (int b = 0; b < 4; ++b) mp[b] += xj[b];
            }
        }
        __syncthreads();
    }
    #pragma unroll
    for (int a = 0; a < 4; ++a)
        #pragma unroll
        for (int b = 0; b < 4; ++b)
            atomicAdd(&g_Sx[(i0 + a) * 64 + (j0 + b)], acc[a][b]);
    if ((tid >> 4) == 0) {
        #pragma unroll
        for (int b = 0; b < 4; ++b) atomicAdd(&g_mx[j0 + b], mp[b]);
    }
}

// ---------------- prelude: per-batch counts + CSR | Sx --------------------
// blocks [0,256): counts + CSR for batch blk; [256,512): Sx.
__global__ __launch_bounds__(256)
void prelude_kernel(const int* __restrict__ nl, const int* __restrict__ bl,
                    const float4* __restrict__ atomF)
{
    __shared__ int hA[ANUM];
    __shared__ int hB[NBNUM];
    __shared__ int offs[ANUM];
    __shared__ int total;
    extern __shared__ float dsm[];

    const int blk = blockIdx.x;
    const int tid = threadIdx.x;

    if (blk >= 256) { sx_body(dsm, atomF, blk - 256); return; }

    const int b = blk;
    if (tid < ANUM) hA[tid] = 0;
    hB[tid] = 0;
    if (tid == 0) total = 0;
    __syncthreads();
    const int base = b * 2048;
    for (int i = tid; i < 2048; i += 256) {
        atomicAdd(&hA[nl[base + i]], 1);
        atomicAdd(&hB[bl[base + i]], 1);
    }
    __syncthreads();
    if (tid < ANUM) {
        int c = hA[tid];
        int o = atomicAdd(&total, c);
        offs[tid] = o;
        g_offs[b * ANUM + tid] = o;
        g_cntA[b * ANUM + tid] = (float)c;
    }
    g_cntB[b * NBNUM + tid] = (float)hB[tid];
    __syncthreads();
    if (tid < ANUM) hA[tid] = 0;   // reuse as cursor
    __syncthreads();
    for (int i = tid; i < 2048; i += 256) {
        int a = nl[base + i];
        int slot = offs[a] + atomicAdd(&hA[a], 1);
        g_csr[base + slot] = bl[base + i];
    }
}

// ---------------- GEMM tile body -------------------------------------------
// SMODE: 0 = none, 1 = fused normalize+leaky (uses g_scale[0]),
//        2 = cnt-weighted stats -> g_sum1/g_sq1
// x is pre-packed at staging into duplicated f32x2 pairs (xs2), removing the
// 8 pack MOVs from the k-loop and the LDS->pack dependency hop.
template<int K, int SMODE>
__device__ __forceinline__
void gemm_body(float* smem,
               const float4* __restrict__ Wg, int wldq, int woffq,
               const float4* __restrict__ X, const float* __restrict__ cnt,
               float* __restrict__ out, int tile)
{
    constexpr int KQ = K / 4;
    float* ws = smem;                                        // K*256 floats
    unsigned long long* xs2 = (unsigned long long*)(smem + K * FPC); // K*64 u64
    float* cw   = (float*)(xs2 + K * 64);                    // 64
    float* ssum = cw + 64;                                   // 256
    float* ssq  = ssum + FPC;                                // 256

    const int tid = threadIdx.x;
    const int r0 = (tid >> 5) * 8;
    const int c0 = (tid & 31) * 8;

    for (int idx = tid; idx < FPC * KQ; idx += 256) {
        int q = idx >> 8;
        int c = idx & 255;
        float4 v = Wg[(size_t)c * wldq + woffq + q];
        ws[(4*q+0)*FPC + c] = v.x;
        ws[(4*q+1)*FPC + c] = v.y;
        ws[(4*q+2)*FPC + c] = v.z;
        ws[(4*q+3)*FPC + c] = v.w;
    }
    for (int idx = tid; idx < 64 * KQ; idx += 256) {
        int lr = idx & 63;
        int q  = idx >> 6;
        float4 v = X[(size_t)(tile * 64 + lr) * KQ + q];
        xs2[(4*q+0)*64 + lr] = pack2(v.x, v.x);
        xs2[(4*q+1)*64 + lr] = pack2(v.y, v.y);
        xs2[(4*q+2)*64 + lr] = pack2(v.z, v.z);
        xs2[(4*q+3)*64 + lr] = pack2(v.w, v.w);
    }
    if (SMODE == 2 && tid < 64) cw[tid] = cnt[tile * 64 + tid];
    float scv[8], shv[8];
    if (SMODE == 1) {
        #pragma unroll
        for (int j = 0; j < 8; ++j) {
            scv[j] = g_scale[0][c0 + j];
            shv[j] = g_shift[0][c0 + j];
        }
    }
    __syncthreads();

    unsigned long long acc[8][4];
    #pragma unroll
    for (int i = 0; i < 8; ++i)
        #pragma unroll
        for (int j = 0; j < 4; ++j) acc[i][j] = 0ull;

    #pragma unroll 2
    for (int k = 0; k < K; ++k) {
        const ulonglong2* xrow = (const ulonglong2*)&xs2[k*64 + r0];
        const ulonglong2 x01 = xrow[0];   // broadcast LDS.128
        const ulonglong2 x23 = xrow[1];
        const ulonglong2 x45 = xrow[2];
        const ulonglong2 x67 = xrow[3];
        const ulonglong2 w0 = *(const ulonglong2*)&ws[k*FPC + c0];
        const ulonglong2 w1 = *(const ulonglong2*)&ws[k*FPC + c0 + 4];
        unsigned long long xp[8] = {x01.x, x01.y, x23.x, x23.y,
                                    x45.x, x45.y, x67.x, x67.y};
        #pragma unroll
        for (int i = 0; i < 8; ++i) {
            fma2(acc[i][0], xp[i], w0.x);
            fma2(acc[i][1], xp[i], w0.y);
            fma2(acc[i][2], xp[i], w1.x);
            fma2(acc[i][3], xp[i], w1.y);
        }
    }

    float sumc[8], sqc[8];
    if (SMODE == 2) {
        #pragma unroll
        for (int j = 0; j < 8; ++j) { sumc[j] = 0.f; sqc[j] = 0.f; }
    }

    #pragma unroll
    for (int i = 0; i < 8; ++i) {
        float y[8];
        #pragma unroll
        for (int j = 0; j < 4; ++j) {
            float2 p = unpack2(acc[i][j]);
            y[2*j]   = p.x;
            y[2*j+1] = p.y;
        }
        size_t row = (size_t)tile * 64 + r0 + i;
        float4* o = (float4*)&out[row * FPC + c0];
        if (SMODE == 1) {
            #pragma unroll
            for (int j = 0; j < 8; ++j) {
                y[j] = y[j] * scv[j] + shv[j];
                y[j] = fmaxf(y[j], SLOPE * y[j]);
            }
            __stcs(o,     make_float4(y[0], y[1], y[2], y[3]));
            __stcs(o + 1, make_float4(y[4], y[5], y[6], y[7]));
        } else {
            if (SMODE == 2) {
                float c = cw[r0 + i];
                #pragma unroll
                for (int j = 0; j < 8; ++j) { sumc[j] += c*y[j]; sqc[j] += c*y[j]*y[j]; }
            }
            o[0] = make_float4(y[0], y[1], y[2], y[3]);
            o[1] = make_float4(y[4], y[5], y[6], y[7]);
        }
    }

    if (SMODE == 2) {
        __syncthreads();
        ssum[tid] = 0.f; ssq[tid] = 0.f;
        __syncthreads();
        #pragma unroll
        for (int j = 0; j < 8; ++j) {
            atomicAdd(&ssum[c0 + j], sumc[j]);
            atomicAdd(&ssq [c0 + j], sqc[j]);
        }
        __syncthreads();
        atomicAdd(&g_sum1[tid], ssum[tid]);
        atomicAdd(&g_sq1[tid],  ssq[tid]);
    }
}

// ---------------- crossdot body: Sab += A_b^T G_b via CSR ------------------
__device__ __forceinline__
void crossdot_body(float* smem, const float4* __restrict__ atomF,
                   const float* __restrict__ bondF, int b)
{
    float (*as)[64] = (float(*)[64])smem;        // 128*64 floats
    float* partial  = smem + 128*64;             // 8*2048 floats
    int*   soffs    = (int*)(partial + 8*2048);  // 128
    int*   scnt     = soffs + 128;               // 128

    const int tid  = threadIdx.x;
    const int lane = tid & 31;
    const int warp = tid >> 5;

    for (int idx = tid; idx < 128*16; idx += 256) {
        int row = idx >> 4, q = idx & 15;
        float4 v = atomF[(size_t)(b*128 + row) * 16 + q];
        *(float4*)&as[row][q*4] = v;
    }
    if (tid < 128) {
        soffs[tid] = g_offs[b * ANUM + tid];
        scnt[tid]  = (int)g_cntA[b * ANUM + tid];
    }
    __syncthreads();

    float acc[64];
    #pragma unroll
    for (int i = 0; i < 64; ++i) acc[i] = 0.f;

    const float* B = bondF + (size_t)b * NBNUM * FB;
    const int* csr = g_csr + (size_t)b * 2048;

    for (int a = warp; a < 128; a += 8) {
        const int off = soffs[a];
        const int cn  = scnt[a];
        float g = 0.f;
        for (int j = 0; j < cn; ++j) {
            int bidx = csr[off + j];
            g += B[bidx * FB + lane];
        }
        #pragma unroll
        for (int i = 0; i < 64; ++i) acc[i] += as[a][i] * g;
    }
    #pragma unroll
    for (int i = 0; i < 64; ++i) partial[warp*2048 + i*32 + lane] = acc[i];
    __syncthreads();
    for (int e = tid; e < 2048; e += 256) {
        float s = 0.f;
        #pragma unroll
        for (int w = 0; w < 8; ++w) s += partial[w*2048 + e];
        atomicAdd(&g_Sab[e], s);   // Sab[i][j], e = i*32 + j
    }
}

// ---------------- mega mid: crossdot | P | Q | atomGEMM+norm ---------------
// blocks [0,256): crossdot; [256,768): P; [768,1792): Q; [1792,2304): atom.
__global__ __launch_bounds__(256, 2)
void mid_kernel(const float4* __restrict__ atomF, const float4* __restrict__ bondF,
                const float4* __restrict__ atomW, const float4* __restrict__ neiW,
                float* __restrict__ out_atom)
{
    extern __shared__ float smem[];
    const int blk = blockIdx.x;
    if (blk < 256) {
        crossdot_body(smem, atomF, (const float*)bondF, blk);
    } else if (blk < 768) {
        gemm_body<64, 2>(smem, neiW, 24, 0, atomF, g_cntA, g_P, blk - 256);
    } else if (blk < 1792) {
        gemm_body<32, 2>(smem, neiW, 24, 16, bondF, g_cntB, g_Q, blk - 768);
    } else {
        gemm_body<64, 1>(smem, atomW, 16, 0, atomF, nullptr, out_atom, blk - 1792);
    }
}

// ---------------- finalize atom scale (analytic via Sx) --------------------
__global__ void finalize_atom_kernel(const float* __restrict__ atom_W,
                                     const float* __restrict__ atom_gamma,
                                     const float* __restrict__ atom_beta)
{
    const int c = blockIdx.x;
    const int t = threadIdx.x;    // 64 threads
    __shared__ float w[64];
    __shared__ float red[64], red2[64];
    w[t] = atom_W[c * 64 + t];
    __syncthreads();
    float v = 0.f;
    #pragma unroll 8
    for (int j = 0; j < 64; ++j) v += g_Sx[t * 64 + j] * w[j];
    red[t]  = w[t] * v;
    red2[t] = w[t] * g_mx[t];
    __syncthreads();
    for (int s = 32; s > 0; s >>= 1) {
        if (t < s) { red[t] += red[t + s]; red2[t] += red2[t + s]; }
        __syncthreads();
    }
    if (t == 0) {
        float n = (float)R_ATOM;
        float mean = red2[0] / n;
        float var  = red[0] / n - mean * mean;
        float sc = atom_gamma[c] * rsqrtf(var + BN_EPS);
        g_scale[0][c] = sc;
        g_shift[0][c] = atom_beta[c] - mean * sc;
    }
}

// ---------------- finalize nei scale (cross via Sab) -----------------------
__global__ void finalize_nei_kernel(const float* __restrict__ nei_W,
                                    const float* __restrict__ nei_gamma,
                                    const float* __restrict__ nei_beta)
{
    const int c = blockIdx.x;
    const int t = threadIdx.x;    // 64 threads
    __shared__ float wb[32];
    __shared__ float red[64];
    if (t < 32) wb[t] = nei_W[c * 96 + 64 + t];
    __syncthreads();
    float v = 0.f;
    #pragma unroll
    for (int j = 0; j < 32; ++j) v += g_Sab[t * 32 + j] * wb[j];
    red[t] = v * nei_W[c * 96 + t];
    __syncthreads();
    for (int s = 32; s > 0; s >>= 1) {
        if (t < s) red[t] += red[t + s];
        __syncthreads();
    }
    if (t == 0) {
        float cross = red[0];
        float n = (float)R_NEI;
        float mean = g_sum1[c] / n;
        float var  = (g_sq1[c] + 2.f * cross) / n - mean * mean;
        float sc = nei_gamma[c] * rsqrtf(var + BN_EPS);
        g_scale[1][c] = sc;
        g_shift[1][c] = nei_beta[c] - mean * sc;
    }
}

// ---------------- nei output: smem-cached P/Q channel-quarters (R10) -------
__global__ __launch_bounds__(512, 2)
void nei_out_kernel(const int* __restrict__ nl, const int* __restrict__ bl,
                    float* __restrict__ out_nei)
{
    extern __shared__ float4 sm4[];
    float4* ps = sm4;                     // 128*16
    float4* qs = sm4 + 128*16;            // 256*16
    int*    sidx = (int*)(qs + 256*16);   // 2048

    const int tid  = threadIdx.x;
    const int blk  = blockIdx.x;
    const int b    = blk >> 2;
    const int qt   = blk & 3;
    const int lane = tid & 31;
    const int warp = tid >> 5;
    const int c16  = lane & 15;

    const float4* P4 = (const float4*)g_P;
    const float4* Q4 = (const float4*)g_Q;

    for (int i = tid; i < 128*16; i += 512) {
        int a = i >> 4, q = i & 15;
        ps[i] = P4[(size_t)(b*128 + a)*64 + qt*16 + q];
    }
    for (int i = tid; i < 256*16; i += 512) {
        int bd = i >> 4, q = i & 15;
        qs[i] = Q4[(size_t)(b*256 + bd)*64 + qt*16 + q];
    }
    for (int i = tid; i < 2048; i += 512) {
        int r = b*2048 + i;
        sidx[i] = nl[r] | (bl[r] << 8);
    }
    float4 s = ((const float4*)g_scale[1])[qt*16 + c16];
    float4 h = ((const float4*)g_shift[1])[qt*16 + c16];
    __syncthreads();

    for (int rp = warp; rp < 1024; rp += 16) {
        int row = rp * 2 + (lane >> 4);
        int pk = sidx[row];
        float4 p = ps[(pk & 255) * 16 + c16];
        float4 q = qs[(pk >> 8) * 16 + c16];
        float4 v;
        v.x = (p.x + q.x) * s.x + h.x;
        v.y = (p.y + q.y) * s.y + h.y;
        v.z = (p.z + q.z) * s.z + h.z;
        v.w = (p.w + q.w) * s.w + h.w;
        v.x = fmaxf(v.x, SLOPE * v.x);
        v.y = fmaxf(v.y, SLOPE * v.y);
        v.z = fmaxf(v.z, SLOPE * v.z);
        v.w = fmaxf(v.w, SLOPE * v.w);
        __stcs((float4*)&out_nei[(size_t)(b*2048 + row)*256 + qt*64 + c16*4], v);
    }
}

// ---------------- launcher ------------------------------------------------
extern "C" void kernel_launch(void* const* d_in, const int* in_sizes, int n_in,
                              void* d_out, int out_size) {
    const float* atom_features = (const float*)d_in[0];
    const float* bond_features = (const float*)d_in[1];
    const int*   atom_nl       = (const int*)  d_in[2];
    const int*   bond_nl       = (const int*)  d_in[3];
    const float* atom_W        = (const float*)d_in[4];
    const float* atom_gamma    = (const float*)d_in[6];
    const float* atom_beta     = (const float*)d_in[7];
    const float* nei_W         = (const float*)d_in[8];
    const float* nei_gamma     = (const float*)d_in[10];
    const float* nei_beta      = (const float*)d_in[11];

    float* out_atom = (float*)d_out;
    float* out_nei  = (float*)d_out + ATOM_OUT_ELEMS;

    const int smemPre = 32 * 64 * (int)sizeof(float);            // 8192
    const int smemMid = SMEM_MID_F * (int)sizeof(float);         // 100608
    const int smemOut = (128*16 + 256*16) * 16 + 2048 * 4;       // 106496
    cudaFuncSetAttribute((const void*)prelude_kernel,
                         cudaFuncAttributeMaxDynamicSharedMemorySize, smemPre);
    cudaFuncSetAttribute((const void*)mid_kernel,
                         cudaFuncAttributeMaxDynamicSharedMemorySize, smemMid);
    cudaFuncSetAttribute((const void*)nei_out_kernel,
                         cudaFuncAttributeMaxDynamicSharedMemorySize, smemOut);

    // 1) zero accumulators
    zero_kernel<<<1, 256>>>();

    // 2) per-batch counts + CSR | atom feature moments (Sx, mx)
    prelude_kernel<<<512, 256, smemPre>>>(atom_nl, bond_nl,
                                          (const float4*)atom_features);

    // 3) atom scale/shift (analytic quadratic form)
    finalize_atom_kernel<<<256, 64>>>(atom_W, atom_gamma, atom_beta);

    // 4) crossdot (Sab) | P-GEMM+wstats | Q-GEMM+wstats | atom GEMM+norm
    mid_kernel<<<2304, 256, smemMid>>>(
        (const float4*)atom_features, (const float4*)bond_features,
        (const float4*)atom_W, (const float4*)nei_W, out_atom);

    // 5) nei scale/shift (cross term via Sab quadratic form)
    finalize_nei_kernel<<<256, 64>>>(nei_W, nei_gamma, nei_beta);

    // 6) nei output: R10-proven quarters, fused normalize+leaky
    nei_out_kernel<<<1024, 512, smemOut>>>(atom_nl, bond_nl, out_nei);
}

// round 14
// speedup vs baseline: 1.2020x; 1.2020x over previous
#include <cuda_runtime.h>
#include <cstdint>
#include <cstddef>

#define BATCH 256
#define ANUM  128
#define NBNUM 256
#define DNUM  16
#define FA    64
#define FB    32
#define FPC   256
#define R_NEI  (BATCH*ANUM*DNUM)   // 524288
#define R_ATOM (BATCH*ANUM)        // 32768
#define R_BOND (BATCH*NBNUM)       // 65536
#define ATOM_OUT_ELEMS ((long long)R_ATOM*FPC)
#define NEI_OUT_ELEMS  ((long long)R_NEI*FPC)
#define BN_EPS 1e-6f
#define SLOPE  0.01f

// ---------------- device scratch ----------------
__device__ float g_P[(size_t)R_ATOM * FPC];   // 33.5 MB
__device__ float g_Q[(size_t)R_BOND * FPC];   // 67 MB
__device__ float g_cntA[R_ATOM];
__device__ float g_cntB[R_BOND];
__device__ int   g_csr[R_NEI];                // per-batch CSR: bond idx lists
__device__ int   g_offs[R_ATOM];              // per-batch CSR offsets
__device__ float g_Sx[64*64];                 // atom 2nd moment
__device__ float g_mx[64];                    // atom 1st moment
__device__ float g_Sab[64*32];                // raw-feature cross moment
__device__ float g_sum1[FPC];                 // nei sum t  (weighted epilogues)
__device__ float g_sq1[FPC];                  // nei sum t^2 (minus cross)
__device__ float g_scale[2][FPC];
__device__ float g_shift[2][FPC];

// Shared-memory budgets (floats), mirroring the body layouts EXACTLY.
#define SMEM_GEMM_F   (64*FPC + 64*64 + 64 + 2*FPC)          // 21056
#define SMEM_CROSS_F  (128*64 + 8*2048 + 128 + 128)          // 24832
#define SMEM_MID_F    (SMEM_CROSS_F > SMEM_GEMM_F ? SMEM_CROSS_F : SMEM_GEMM_F)

// ---------------- packed f32x2 helpers ----------------
__device__ __forceinline__ unsigned long long pack2(float lo, float hi) {
    unsigned long long r;
    asm("mov.b64 %0, {%1,%2};" : "=l"(r) : "f"(lo), "f"(hi));
    return r;
}
__device__ __forceinline__ void fma2(unsigned long long& d,
                                     unsigned long long a,
                                     unsigned long long b) {
    asm("fma.rn.f32x2 %0, %1, %2, %0;" : "+l"(d) : "l"(a), "l"(b));
}
__device__ __forceinline__ float2 unpack2(unsigned long long v) {
    float2 r;
    asm("mov.b64 {%0,%1}, %2;" : "=f"(r.x), "=f"(r.y) : "l"(v));
    return r;
}

// ---------------- zero scratch ----------------
__global__ void zero_kernel() {
    const int tid = threadIdx.x;
    for (int i = tid; i < 64*64; i += 256) g_Sx[i] = 0.f;
    for (int i = tid; i < 64*32; i += 256) g_Sab[i] = 0.f;
    if (tid < 64) g_mx[tid] = 0.f;
    g_sum1[tid] = 0.f;
    g_sq1[tid]  = 0.f;
}

// ---------------- Sx body: Sx += X_blk^T X_blk, mx += sum(X_blk) ----------
__device__ __forceinline__
void sx_body(float* smem, const float4* __restrict__ X, int vbid)
{
    float (*xs)[64] = (float(*)[64])smem;   // 32 x 64
    const int tid = threadIdx.x;
    const int i0 = (tid >> 4) * 4;
    const int j0 = (tid & 15) * 4;

    float acc[4][4];
    #pragma unroll
    for (int a = 0; a < 4; ++a)
        #pragma unroll
        for (int b = 0; b < 4; ++b) acc[a][b] = 0.f;
    float mp[4] = {0.f, 0.f, 0.f, 0.f};

    const int base = vbid * 128;
    for (int s = 0; s < 128; s += 32) {
        for (int idx = tid; idx < 512; idx += 256) {
            int row = idx >> 4, q = idx & 15;
            float4 v = X[(size_t)(base + s + row) * 16 + q];
            *(float4*)&xs[row][q * 4] = v;
        }
        __syncthreads();
        for (int k = 0; k < 32; ++k) {
            float xi[4], xj[4];
            #pragma unroll
            for (int a = 0; a < 4; ++a) { xi[a] = xs[k][i0 + a]; xj[a] = xs[k][j0 + a]; }
            #pragma unroll
            for (int a = 0; a < 4; ++a)
                #pragma unroll
                for (int b = 0; b < 4; ++b) acc[a][b] += xi[a] * xj[b];
            if ((tid >> 4) == 0) {
                #pragma unroll
                for (int b = 0; b < 4; ++b) mp[b] += xj[b];
            }
        }
        __syncthreads();
    }
    #pragma unroll
    for (int a = 0; a < 4; ++a)
        #pragma unroll
        for (int b = 0; b < 4; ++b)
            atomicAdd(&g_Sx[(i0 + a) * 64 + (j0 + b)], acc[a][b]);
    if ((tid >> 4) == 0) {
        #pragma unroll
        for (int b = 0; b < 4; ++b) atomicAdd(&g_mx[j0 + b], mp[b]);
    }
}

// ---------------- prelude: per-batch counts + CSR | Sx --------------------
// blocks [0,256): counts + CSR for batch blk; [256,512): Sx.
__global__ __launch_bounds__(256)
void prelude_kernel(const int* __restrict__ nl, const int* __restrict__ bl,
                    const float4* __restrict__ atomF)
{
    __shared__ int hA[ANUM];
    __shared__ int hB[NBNUM];
    __shared__ int offs[ANUM];
    __shared__ int total;
    extern __shared__ float dsm[];

    const int blk = blockIdx.x;
    const int tid = threadIdx.x;

    if (blk >= 256) { sx_body(dsm, atomF, blk - 256); return; }

    const int b = blk;
    if (tid < ANUM) hA[tid] = 0;
    hB[tid] = 0;
    if (tid == 0) total = 0;
    __syncthreads();
    const int base = b * 2048;
    for (int i = tid; i < 2048; i += 256) {
        atomicAdd(&hA[nl[base + i]], 1);
        atomicAdd(&hB[bl[base + i]], 1);
    }
    __syncthreads();
    if (tid < ANUM) {
        int c = hA[tid];
        int o = atomicAdd(&total, c);
        offs[tid] = o;
        g_offs[b * ANUM + tid] = o;
        g_cntA[b * ANUM + tid] = (float)c;
    }
    g_cntB[b * NBNUM + tid] = (float)hB[tid];
    __syncthreads();
    if (tid < ANUM) hA[tid] = 0;   // reuse as cursor
    __syncthreads();
    for (int i = tid; i < 2048; i += 256) {
        int a = nl[base + i];
        int slot = offs[a] + atomicAdd(&hA[a], 1);
        g_csr[base + slot] = bl[base + i];
    }
}

// ---------------- GEMM tile body -------------------------------------------
// SMODE: 0 = none, 1 = fused normalize+leaky (uses g_scale[0]),
//        2 = cnt-weighted stats -> g_sum1/g_sq1
// Channel mapping: thread owns channels [lane*4, lane*4+4) and
// [128+lane*4, 128+lane*4+4). w LDS.128 and output STG.128 are then fully
// coalesced (16B lane stride) instead of segmented (32B stride).
template<int K, int SMODE>
__device__ __forceinline__
void gemm_body(float* smem,
               const float4* __restrict__ Wg, int wldq, int woffq,
               const float4* __restrict__ X, const float* __restrict__ cnt,
               float* __restrict__ out, int tile)
{
    constexpr int KQ = K / 4;
    float* ws = smem;               // K*256
    float* xs = smem + K * FPC;     // K*64
    float* cw   = xs + K * 64;      // 64
    float* ssum = cw + 64;          // 256
    float* ssq  = ssum + FPC;       // 256

    const int tid = threadIdx.x;
    const int lane = tid & 31;
    const int r0 = (tid >> 5) * 8;   // rows: uniform per warp (broadcast x)
    const int cq = lane * 4;         // channels cq..cq+3 and 128+cq..128+cq+3

    for (int idx = tid; idx < FPC * KQ; idx += 256) {
        int q = idx >> 8;
        int c = idx & 255;
        float4 v = Wg[(size_t)c * wldq + woffq + q];
        ws[(4*q+0)*FPC + c] = v.x;
        ws[(4*q+1)*FPC + c] = v.y;
        ws[(4*q+2)*FPC + c] = v.z;
        ws[(4*q+3)*FPC + c] = v.w;
    }
    for (int idx = tid; idx < 64 * KQ; idx += 256) {
        int lr = idx & 63;
        int q  = idx >> 6;
        float4 v = X[(size_t)(tile * 64 + lr) * KQ + q];
        xs[(4*q+0)*64 + lr] = v.x;
        xs[(4*q+1)*64 + lr] = v.y;
        xs[(4*q+2)*64 + lr] = v.z;
        xs[(4*q+3)*64 + lr] = v.w;
    }
    if (SMODE == 2 && tid < 64) cw[tid] = cnt[tile * 64 + tid];
    float scv[8], shv[8];
    if (SMODE == 1) {
        #pragma unroll
        for (int j = 0; j < 4; ++j) {
            scv[j]   = g_scale[0][cq + j];
            shv[j]   = g_shift[0][cq + j];
            scv[4+j] = g_scale[0][128 + cq + j];
            shv[4+j] = g_shift[0][128 + cq + j];
        }
    }
    __syncthreads();

    // acc[i][0]: ch cq+0,1   acc[i][1]: ch cq+2,3
    // acc[i][2]: ch 128+cq+0,1   acc[i][3]: ch 128+cq+2,3
    unsigned long long acc[8][4];
    #pragma unroll
    for (int i = 0; i < 8; ++i)
        #pragma unroll
        for (int j = 0; j < 4; ++j) acc[i][j] = 0ull;

    #pragma unroll 2
    for (int k = 0; k < K; ++k) {
        const float4 xa = *(const float4*)&xs[k*64 + r0];       // warp-broadcast
        const float4 xb = *(const float4*)&xs[k*64 + r0 + 4];
        const ulonglong2 w0 = *(const ulonglong2*)&ws[k*FPC + cq];        // coalesced
        const ulonglong2 w1 = *(const ulonglong2*)&ws[k*FPC + 128 + cq];  // coalesced
        unsigned long long xp[8];
        xp[0] = pack2(xa.x, xa.x); xp[1] = pack2(xa.y, xa.y);
        xp[2] = pack2(xa.z, xa.z); xp[3] = pack2(xa.w, xa.w);
        xp[4] = pack2(xb.x, xb.x); xp[5] = pack2(xb.y, xb.y);
        xp[6] = pack2(xb.z, xb.z); xp[7] = pack2(xb.w, xb.w);
        #pragma unroll
        for (int i = 0; i < 8; ++i) {
            fma2(acc[i][0], xp[i], w0.x);
            fma2(acc[i][1], xp[i], w0.y);
            fma2(acc[i][2], xp[i], w1.x);
            fma2(acc[i][3], xp[i], w1.y);
        }
    }

    float sumc[8], sqc[8];
    if (SMODE == 2) {
        #pragma unroll
        for (int j = 0; j < 8; ++j) { sumc[j] = 0.f; sqc[j] = 0.f; }
    }

    #pragma unroll
    for (int i = 0; i < 8; ++i) {
        float y[8];
        #pragma unroll
        for (int j = 0; j < 4; ++j) {
            float2 p = unpack2(acc[i][j]);
            y[2*j]   = p.x;
            y[2*j+1] = p.y;
        }
        size_t row = (size_t)tile * 64 + r0 + i;
        float4* o0 = (float4*)&out[row * FPC + cq];
        float4* o1 = (float4*)&out[row * FPC + 128 + cq];
        if (SMODE == 1) {
            #pragma unroll
            for (int j = 0; j < 8; ++j) {
                y[j] = y[j] * scv[j] + shv[j];
                y[j] = fmaxf(y[j], SLOPE * y[j]);
            }
            __stcs(o0, make_float4(y[0], y[1], y[2], y[3]));
            __stcs(o1, make_float4(y[4], y[5], y[6], y[7]));
        } else {
            if (SMODE == 2) {
                float c = cw[r0 + i];
                #pragma unroll
                for (int j = 0; j < 8; ++j) { sumc[j] += c*y[j]; sqc[j] += c*y[j]*y[j]; }
            }
            *o0 = make_float4(y[0], y[1], y[2], y[3]);
            *o1 = make_float4(y[4], y[5], y[6], y[7]);
        }
    }

    if (SMODE == 2) {
        __syncthreads();
        ssum[tid] = 0.f; ssq[tid] = 0.f;
        __syncthreads();
        #pragma unroll
        for (int j = 0; j < 4; ++j) {
            atomicAdd(&ssum[cq + j],       sumc[j]);
            atomicAdd(&ssum[128 + cq + j], sumc[4+j]);
            atomicAdd(&ssq [cq + j],       sqc[j]);
            atomicAdd(&ssq [128 + cq + j], sqc[4+j]);
        }
        __syncthreads();
        atomicAdd(&g_sum1[tid], ssum[tid]);
        atomicAdd(&g_sq1[tid],  ssq[tid]);
    }
}

// ---------------- crossdot body: Sab += A_b^T G_b via CSR ------------------
__device__ __forceinline__
void crossdot_body(float* smem, const float4* __restrict__ atomF,
                   const float* __restrict__ bondF, int b)
{
    float (*as)[64] = (float(*)[64])smem;        // 128*64 floats
    float* partial  = smem + 128*64;             // 8*2048 floats
    int*   soffs    = (int*)(partial + 8*2048);  // 128
    int*   scnt     = soffs + 128;               // 128

    const int tid  = threadIdx.x;
    const int lane = tid & 31;
    const int warp = tid >> 5;

    for (int idx = tid; idx < 128*16; idx += 256) {
        int row = idx >> 4, q = idx & 15;
        float4 v = atomF[(size_t)(b*128 + row) * 16 + q];
        *(float4*)&as[row][q*4] = v;
    }
    if (tid < 128) {
        soffs[tid] = g_offs[b * ANUM + tid];
        scnt[tid]  = (int)g_cntA[b * ANUM + tid];
    }
    __syncthreads();

    float acc[64];
    #pragma unroll
    for (int i = 0; i < 64; ++i) acc[i] = 0.f;

    const float* B = bondF + (size_t)b * NBNUM * FB;
    const int* csr = g_csr + (size_t)b * 2048;

    for (int a = warp; a < 128; a += 8) {
        const int off = soffs[a];
        const int cn  = scnt[a];
        float g = 0.f;
        for (int j = 0; j < cn; ++j) {
            int bidx = csr[off + j];
            g += B[bidx * FB + lane];
        }
        #pragma unroll
        for (int i = 0; i < 64; ++i) acc[i] += as[a][i] * g;
    }
    #pragma unroll
    for (int i = 0; i < 64; ++i) partial[warp*2048 + i*32 + lane] = acc[i];
    __syncthreads();
    for (int e = tid; e < 2048; e += 256) {
        float s = 0.f;
        #pragma unroll
        for (int w = 0; w < 8; ++w) s += partial[w*2048 + e];
        atomicAdd(&g_Sab[e], s);   // Sab[i][j], e = i*32 + j
    }
}

// ---------------- mega mid: crossdot | P | Q | atomGEMM+norm ---------------
// blocks [0,256): crossdot; [256,768): P; [768,1792): Q; [1792,2304): atom.
__global__ __launch_bounds__(256, 2)
void mid_kernel(const float4* __restrict__ atomF, const float4* __restrict__ bondF,
                const float4* __restrict__ atomW, const float4* __restrict__ neiW,
                float* __restrict__ out_atom)
{
    extern __shared__ float smem[];
    const int blk = blockIdx.x;
    if (blk < 256) {
        crossdot_body(smem, atomF, (const float*)bondF, blk);
    } else if (blk < 768) {
        gemm_body<64, 2>(smem, neiW, 24, 0, atomF, g_cntA, g_P, blk - 256);
    } else if (blk < 1792) {
        gemm_body<32, 2>(smem, neiW, 24, 16, bondF, g_cntB, g_Q, blk - 768);
    } else {
        gemm_body<64, 1>(smem, atomW, 16, 0, atomF, nullptr, out_atom, blk - 1792);
    }
}

// ---------------- finalize atom scale (analytic via Sx) --------------------
__global__ void finalize_atom_kernel(const float* __restrict__ atom_W,
                                     const float* __restrict__ atom_gamma,
                                     const float* __restrict__ atom_beta)
{
    const int c = blockIdx.x;
    const int t = threadIdx.x;    // 64 threads
    __shared__ float w[64];
    __shared__ float red[64], red2[64];
    w[t] = atom_W[c * 64 + t];
    __syncthreads();
    float v = 0.f;
    #pragma unroll 8
    for (int j = 0; j < 64; ++j) v += g_Sx[t * 64 + j] * w[j];
    red[t]  = w[t] * v;
    red2[t] = w[t] * g_mx[t];
    __syncthreads();
    for (int s = 32; s > 0; s >>= 1) {
        if (t < s) { red[t] += red[t + s]; red2[t] += red2[t + s]; }
        __syncthreads();
    }
    if (t == 0) {
        float n = (float)R_ATOM;
        float mean = red2[0] / n;
        float var  = red[0] / n - mean * mean;
        float sc = atom_gamma[c] * rsqrtf(var + BN_EPS);
        g_scale[0][c] = sc;
        g_shift[0][c] = atom_beta[c] - mean * sc;
    }
}

// ---------------- finalize nei scale (cross via Sab) -----------------------
__global__ void finalize_nei_kernel(const float* __restrict__ nei_W,
                                    const float* __restrict__ nei_gamma,
                                    const float* __restrict__ nei_beta)
{
    const int c = blockIdx.x;
    const int t = threadIdx.x;    // 64 threads
    __shared__ float wb[32];
    __shared__ float red[64];
    if (t < 32) wb[t] = nei_W[c * 96 + 64 + t];
    __syncthreads();
    float v = 0.f;
    #pragma unroll
    for (int j = 0; j < 32; ++j) v += g_Sab[t * 32 + j] * wb[j];
    red[t] = v * nei_W[c * 96 + t];
    __syncthreads();
    for (int s = 32; s > 0; s >>= 1) {
        if (t < s) red[t] += red[t + s];
        __syncthreads();
    }
    if (t == 0) {
        float cross = red[0];
        float n = (float)R_NEI;
        float mean = g_sum1[c] / n;
        float var  = (g_sq1[c] + 2.f * cross) / n - mean * mean;
        float sc = nei_gamma[c] * rsqrtf(var + BN_EPS);
        g_scale[1][c] = sc;
        g_shift[1][c] = nei_beta[c] - mean * sc;
    }
}

// ---------------- nei output: smem-cached P/Q channel-quarters (R10) -------
__global__ __launch_bounds__(512, 2)
void nei_out_kernel(const int* __restrict__ nl, const int* __restrict__ bl,
                    float* __restrict__ out_nei)
{
    extern __shared__ float4 sm4[];
    float4* ps = sm4;                     // 128*16
    float4* qs = sm4 + 128*16;            // 256*16
    int*    sidx = (int*)(qs + 256*16);   // 2048

    const int tid  = threadIdx.x;
    const int blk  = blockIdx.x;
    const int b    = blk >> 2;
    const int qt   = blk & 3;
    const int lane = tid & 31;
    const int warp = tid >> 5;
    const int c16  = lane & 15;

    const float4* P4 = (const float4*)g_P;
    const float4* Q4 = (const float4*)g_Q;

    for (int i = tid; i < 128*16; i += 512) {
        int a = i >> 4, q = i & 15;
        ps[i] = P4[(size_t)(b*128 + a)*64 + qt*16 + q];
    }
    for (int i = tid; i < 256*16; i += 512) {
        int bd = i >> 4, q = i & 15;
        qs[i] = Q4[(size_t)(b*256 + bd)*64 + qt*16 + q];
    }
    for (int i = tid; i < 2048; i += 512) {
        int r = b*2048 + i;
        sidx[i] = nl[r] | (bl[r] << 8);
    }
    float4 s = ((const float4*)g_scale[1])[qt*16 + c16];
    float4 h = ((const float4*)g_shift[1])[qt*16 + c16];
    __syncthreads();

    for (int rp = warp; rp < 1024; rp += 16) {
        int row = rp * 2 + (lane >> 4);
        int pk = sidx[row];
        float4 p = ps[(pk & 255) * 16 + c16];
        float4 q = qs[(pk >> 8) * 16 + c16];
        float4 v;
        v.x = (p.x + q.x) * s.x + h.x;
        v.y = (p.y + q.y) * s.y + h.y;
        v.z = (p.z + q.z) * s.z + h.z;
        v.w = (p.w + q.w) * s.w + h.w;
        v.x = fmaxf(v.x, SLOPE * v.x);
        v.y = fmaxf(v.y, SLOPE * v.y);
        v.z = fmaxf(v.z, SLOPE * v.z);
        v.w = fmaxf(v.w, SLOPE * v.w);
        __stcs((float4*)&out_nei[(size_t)(b*2048 + row)*256 + qt*64 + c16*4], v);
    }
}

// ---------------- launcher ------------------------------------------------
extern "C" void kernel_launch(void* const* d_in, const int* in_sizes, int n_in,
                              void* d_out, int out_size) {
    const float* atom_features = (const float*)d_in[0];
    const float* bond_features = (const float*)d_in[1];
    const int*   atom_nl       = (const int*)  d_in[2];
    const int*   bond_nl       = (const int*)  d_in[3];
    const float* atom_W        = (const float*)d_in[4];
    const float* atom_gamma    = (const float*)d_in[6];
    const float* atom_beta     = (const float*)d_in[7];
    const float* nei_W         = (const float*)d_in[8];
    const float* nei_gamma     = (const float*)d_in[10];
    const float* nei_beta      = (const float*)d_in[11];

    float* out_atom = (float*)d_out;
    float* out_nei  = (float*)d_out + ATOM_OUT_ELEMS;

    const int smemPre = 32 * 64 * (int)sizeof(float);            // 8192
    const int smemMid = SMEM_MID_F * (int)sizeof(float);         // 99328
    const int smemOut = (128*16 + 256*16) * 16 + 2048 * 4;       // 106496
    cudaFuncSetAttribute((const void*)prelude_kernel,
                         cudaFuncAttributeMaxDynamicSharedMemorySize, smemPre);
    cudaFuncSetAttribute((const void*)mid_kernel,
                         cudaFuncAttributeMaxDynamicSharedMemorySize, smemMid);
    cudaFuncSetAttribute((const void*)nei_out_kernel,
                         cudaFuncAttributeMaxDynamicSharedMemorySize, smemOut);

    // 1) zero accumulators
    zero_kernel<<<1, 256>>>();

    // 2) per-batch counts + CSR | atom feature moments (Sx, mx)
    prelude_kernel<<<512, 256, smemPre>>>(atom_nl, bond_nl,
                                          (const float4*)atom_features);

    // 3) atom scale/shift (analytic quadratic form)
    finalize_atom_kernel<<<256, 64>>>(atom_W, atom_gamma, atom_beta);

    // 4) crossdot (Sab) | P-GEMM+wstats | Q-GEMM+wstats | atom GEMM+norm
    mid_kernel<<<2304, 256, smemMid>>>(
        (const float4*)atom_features, (const float4*)bond_features,
        (const float4*)atom_W, (const float4*)nei_W, out_atom);

    // 5) nei scale/shift (cross term via Sab quadratic form)
    finalize_nei_kernel<<<256, 64>>>(nei_W, nei_gamma, nei_beta);

    // 6) nei output: R10-proven quarters, fused normalize+leaky
    nei_out_kernel<<<1024, 512, smemOut>>>(atom_nl, bond_nl, out_nei);
}